// round 11
// baseline (speedup 1.0000x reference)
#include <cuda_runtime.h>

// Problem constants
namespace {
constexpr int B  = 4;
constexpr int S  = 1024;
constexpr int DM = 512;
constexpr int DA = 512;
constexpr int H  = 8;
constexpr int F  = 16;
}

// Scratch (static device globals -- no allocations allowed)
__device__ float g_qp [B * S * DA];      // 8 MB
__device__ float g_kp [B * S * DA];      // 8 MB
__device__ float g_vp [B * S * DA];      // 8 MB
__device__ float g_x  [B * S * H * F];   // 2 MB
__device__ float g_ctx[B * S * DA];      // 8 MB

// ---------------------------------------------------------------------------
// tf32 helpers
// ---------------------------------------------------------------------------
__device__ __forceinline__ unsigned f2tf(float f) {
    unsigned u;
    asm("cvt.rna.tf32.f32 %0, %1;" : "=r"(u) : "f"(f));
    return u;
}

__device__ __forceinline__ void mma_tf32(float c[4],
                                         unsigned a0, unsigned a1, unsigned a2, unsigned a3,
                                         unsigned b0, unsigned b1) {
    asm volatile(
        "mma.sync.aligned.m16n8k8.row.col.f32.tf32.tf32.f32 "
        "{%0,%1,%2,%3}, {%4,%5,%6,%7}, {%8,%9}, {%0,%1,%2,%3};"
        : "+f"(c[0]), "+f"(c[1]), "+f"(c[2]), "+f"(c[3])
        : "r"(a0), "r"(a1), "r"(a2), "r"(a3), "r"(b0), "r"(b1));
}

// ---------------------------------------------------------------------------
// 64x64-tile tf32 GEMM body: C[m0:64, n0:64] = A[M,K] @ W[K,N] + bias
// 128 threads (4 warps, warp-tile 32x32), BK=16, reg-prefetch double buffer.
// ---------------------------------------------------------------------------
__device__ __forceinline__ void gemm64_body(
    const float* __restrict__ A, const float* __restrict__ W,
    const float* __restrict__ bias, float* __restrict__ C,
    int N, int K, int m0, int n0)
{
    constexpr int AS = 20;   // As[m][k], 16+4
    constexpr int BS = 72;   // Bs[k][n], 64+8
    __shared__ unsigned As[64 * AS];
    __shared__ unsigned Bs[16 * BS];

    const int tid  = threadIdx.x;
    const int warp = tid >> 5;
    const int lane = tid & 31;
    const int gid  = lane >> 2;
    const int tig  = lane & 3;
    const int wm   = (warp & 1) * 32;
    const int wn   = (warp >> 1) * 32;

    float4 ra[2], rb[2];
#pragma unroll
    for (int p = 0; p < 2; p++) {
        const int ia = tid + p * 128;
        ra[p] = *(const float4*)&A[(size_t)(m0 + (ia >> 2)) * K + (ia & 3) * 4];
        const int ib = tid + p * 128;
        rb[p] = *(const float4*)&W[(size_t)(ib >> 4) * N + n0 + (ib & 15) * 4];
    }

    float acc[2][4][4] = {};

    for (int k0 = 0; k0 < K; k0 += 16) {
#pragma unroll
        for (int p = 0; p < 2; p++) {
            const int ia = tid + p * 128;
            unsigned* pa = &As[(ia >> 2) * AS + (ia & 3) * 4];
            pa[0] = f2tf(ra[p].x); pa[1] = f2tf(ra[p].y);
            pa[2] = f2tf(ra[p].z); pa[3] = f2tf(ra[p].w);
            const int ib = tid + p * 128;
            unsigned* pb = &Bs[(ib >> 4) * BS + (ib & 15) * 4];
            pb[0] = f2tf(rb[p].x); pb[1] = f2tf(rb[p].y);
            pb[2] = f2tf(rb[p].z); pb[3] = f2tf(rb[p].w);
        }
        __syncthreads();
        if (k0 + 16 < K) {
#pragma unroll
            for (int p = 0; p < 2; p++) {
                const int ia = tid + p * 128;
                ra[p] = *(const float4*)&A[(size_t)(m0 + (ia >> 2)) * K + k0 + 16 + (ia & 3) * 4];
                const int ib = tid + p * 128;
                rb[p] = *(const float4*)&W[(size_t)(k0 + 16 + (ib >> 4)) * N + n0 + (ib & 15) * 4];
            }
        }
#pragma unroll
        for (int ks = 0; ks < 2; ks++) {
            unsigned afr[2][4];
#pragma unroll
            for (int mi = 0; mi < 2; mi++) {
                const int mr = wm + mi * 16 + gid;
                afr[mi][0] = As[mr * AS + ks * 8 + tig];
                afr[mi][1] = As[(mr + 8) * AS + ks * 8 + tig];
                afr[mi][2] = As[mr * AS + ks * 8 + tig + 4];
                afr[mi][3] = As[(mr + 8) * AS + ks * 8 + tig + 4];
            }
            unsigned bfr[4][2];
#pragma unroll
            for (int ni = 0; ni < 4; ni++) {
                const int nc = wn + ni * 8 + gid;
                bfr[ni][0] = Bs[(ks * 8 + tig) * BS + nc];
                bfr[ni][1] = Bs[(ks * 8 + tig + 4) * BS + nc];
            }
#pragma unroll
            for (int mi = 0; mi < 2; mi++)
#pragma unroll
                for (int ni = 0; ni < 4; ni++)
                    mma_tf32(acc[mi][ni], afr[mi][0], afr[mi][1], afr[mi][2], afr[mi][3],
                             bfr[ni][0], bfr[ni][1]);
        }
        __syncthreads();
    }

#pragma unroll
    for (int mi = 0; mi < 2; mi++) {
        const int row = m0 + wm + mi * 16 + gid;
#pragma unroll
        for (int ni = 0; ni < 4; ni++) {
            const int col = n0 + wn + ni * 8 + 2 * tig;
            const float2 bb = *(const float2*)&bias[col];
            float2 o0, o1;
            o0.x = acc[mi][ni][0] + bb.x; o0.y = acc[mi][ni][1] + bb.y;
            o1.x = acc[mi][ni][2] + bb.x; o1.y = acc[mi][ni][3] + bb.y;
            *(float2*)&C[(size_t)row * N + col]       = o0;
            *(float2*)&C[(size_t)(row + 8) * N + col] = o1;
        }
    }
}

// q/k/v projections batched over blockIdx.z
__global__ __launch_bounds__(128) void qkv_proj_kernel(
    const float* __restrict__ q, const float* __restrict__ k, const float* __restrict__ v,
    const float* __restrict__ Wq, const float* __restrict__ bq,
    const float* __restrict__ Wk, const float* __restrict__ bk,
    const float* __restrict__ Wv, const float* __restrict__ bv,
    float* __restrict__ qp, float* __restrict__ kp, float* __restrict__ vp)
{
    const int z = blockIdx.z;
    const float* A    = (z == 0) ? q  : (z == 1) ? k  : v;
    const float* W    = (z == 0) ? Wq : (z == 1) ? Wk : Wv;
    const float* bias = (z == 0) ? bq : (z == 1) ? bk : bv;
    float*       C    = (z == 0) ? qp : (z == 1) ? kp : vp;
    gemm64_body(A, W, bias, C, DA, DM, blockIdx.y * 64, blockIdx.x * 64);
}

// generic single GEMM (x projection, output projection)
__global__ __launch_bounds__(128) void gemm64_kernel(
    const float* __restrict__ A, const float* __restrict__ W,
    const float* __restrict__ bias, float* __restrict__ C, int N, int K)
{
    gemm64_body(A, W, bias, C, N, K, blockIdx.y * 64, blockIdx.x * 64);
}

// ---------------------------------------------------------------------------
// xdiff bias: logits[b,h,q,k] = 0.5 * sum_f xdiff[b,q,k,f] * x[b,q,h*F+f]
// ---------------------------------------------------------------------------
__global__ __launch_bounds__(256) void xbias_kernel(
    const float* __restrict__ xdiff, const float* __restrict__ xg,
    float* __restrict__ logits)
{
    __shared__ float xh[H * F];
    const int bq  = blockIdx.x;
    const int b   = bq >> 10;
    const int qi  = bq & 1023;
    const int tid = threadIdx.x;
    if (tid < H * F) xh[tid] = xg[(size_t)bq * (H * F) + tid];
    __syncthreads();
    const float* xd = xdiff + (size_t)bq * S * F;
#pragma unroll
    for (int kt = 0; kt < 4; kt++) {
        const int k = kt * 256 + tid;
        const float4* src = (const float4*)&xd[(size_t)k * F];
        const float4 t0 = src[0], t1 = src[1], t2 = src[2], t3 = src[3];
        const float xv[16] = {t0.x, t0.y, t0.z, t0.w, t1.x, t1.y, t1.z, t1.w,
                              t2.x, t2.y, t2.z, t2.w, t3.x, t3.y, t3.z, t3.w};
#pragma unroll
        for (int h = 0; h < H; h++) {
            float s = 0.0f;
#pragma unroll
            for (int f = 0; f < F; f++) s = fmaf(xv[f], xh[h * F + f], s);
            logits[((size_t)(b * H + h) * S + qi) * S + k] = 0.5f * s;
        }
    }
}

// ---------------------------------------------------------------------------
// Fused attention v3: q-tile 16 rows, 256 threads / 8 warps, 64-key chunks,
// double-buffered. 108KB smem -> 2 CTAs/SM (50% occ).
//   acc = bias (prefetched LDG) + QK^T (Q frags in regs) -> STS to L
//   softmax(L) -> attn gmem (float) + L (tf32 bits)
//   PV: ks-split across 2 warp groups, smem partial reduce -> ctx
// smem: L 16x1044 + Qs/P 16x68 + 2 x (64x72) = 108,032 B
// ---------------------------------------------------------------------------
namespace {
constexpr int QT   = 16;     // q rows per CTA
constexpr int CH   = 64;     // keys per chunk
constexpr int NCH  = S / CH; // 16 chunks
constexpr int LSTR = 1044;
constexpr int QSTR = 68;
constexpr int KSTK = 68;     // K-phase layout stride inside buffer
constexpr int KSTV = 72;     // V-phase layout stride
constexpr int BUFW = CH * KSTV;
constexpr int FATTN_SMEM = (QT * LSTR + QT * QSTR + 2 * BUFW) * 4;
}

__global__ __launch_bounds__(256) void fattn_kernel(
    const float* __restrict__ qp, const float* __restrict__ kp,
    const float* __restrict__ vp, float* __restrict__ attn,
    float* __restrict__ ctx)
{
    extern __shared__ float smem[];
    float*    L  = smem;                               // QT x LSTR
    unsigned* Lu = (unsigned*)smem;
    unsigned* Qs = (unsigned*)(smem + QT * LSTR);      // QT x QSTR (Q; later P)
    float*    P  = (float*)Qs;
    unsigned* KV = Qs + QT * QSTR;                     // 2 x BUFW

    const int tid  = threadIdx.x;
    const int warp = tid >> 5;          // 0..7
    const int lane = tid & 31;
    const int gid  = lane >> 2;
    const int tig  = lane & 3;

    const int bh = blockIdx.y;           // b*H + h
    const int b  = bh >> 3;
    const int h  = bh & 7;
    const int q0 = blockIdx.x * QT;

    const size_t bh_row0 = ((size_t)bh * S + q0) * S;

    const float* Kb = kp + (size_t)b * S * DA + h * 64;
    const float* Vb = vp + (size_t)b * S * DA + h * 64;

    // ---- Q tile -> Qs (prescaled, tf32): 16 rows x 16 float4 = 256 threads ----
    {
        const int row = tid >> 4;
        const int c4  = (tid & 15) * 4;
        const float4 v = *(const float4*)&qp[(size_t)(b * S + q0 + row) * DA + h * 64 + c4];
        unsigned* p = &Qs[row * QSTR + c4];
        p[0] = f2tf(v.x * 0.125f); p[1] = f2tf(v.y * 0.125f);
        p[2] = f2tf(v.z * 0.125f); p[3] = f2tf(v.w * 0.125f);
    }

    float4 st[4];
    // ---- preload K chunk 0 (LDG before the sync; STS into buf0) ----
#pragma unroll
    for (int p = 0; p < 4; p++) {
        const int i = tid + p * 256;     // 0..1023 = 64 rows x 16 float4
        st[p] = *(const float4*)&Kb[(size_t)(i >> 4) * DA + (i & 15) * 4];
    }
#pragma unroll
    for (int p = 0; p < 4; p++) {
        const int i = tid + p * 256;
        uint4 u;
        u.x = f2tf(st[p].x); u.y = f2tf(st[p].y); u.z = f2tf(st[p].z); u.w = f2tf(st[p].w);
        *(uint4*)&KV[(i >> 4) * KSTK + (i & 15) * 4] = u;
    }

    // ---- prefetch bias for chunk 0 ----
    const int colw = warp * 8 + tig * 2;   // this warp's 8 cols within a chunk
    float2 bp0, bp1;
    bp0 = *(const float2*)&attn[bh_row0 + (size_t)gid * S + colw];
    bp1 = *(const float2*)&attn[bh_row0 + (size_t)(gid + 8) * S + colw];

    __syncthreads();

    // ---- hoist Q fragments into registers (rows gid / gid+8) ----
    unsigned qa[8][4];
#pragma unroll
    for (int ks = 0; ks < 8; ks++) {
        qa[ks][0] = Qs[gid * QSTR + ks * 8 + tig];
        qa[ks][1] = Qs[(gid + 8) * QSTR + ks * 8 + tig];
        qa[ks][2] = Qs[gid * QSTR + ks * 8 + tig + 4];
        qa[ks][3] = Qs[(gid + 8) * QSTR + ks * 8 + tig + 4];
    }

    // ---- QK^T: acc = bias + Q K^T, one 64-key chunk at a time ----
    for (int kt = 0; kt < NCH; kt++) {
        const unsigned* cur = KV + (kt & 1) * BUFW;

        // prefetch next K chunk (gmem)
        if (kt < NCH - 1) {
            const int kbase = (kt + 1) * CH;
#pragma unroll
            for (int p = 0; p < 4; p++) {
                const int i = tid + p * 256;
                st[p] = *(const float4*)&Kb[(size_t)(kbase + (i >> 4)) * DA + (i & 15) * 4];
            }
        }

        float acc[4];
        acc[0] = bp0.x; acc[1] = bp0.y; acc[2] = bp1.x; acc[3] = bp1.y;

        // prefetch bias for next chunk
        if (kt < NCH - 1) {
            const int colb = (kt + 1) * CH + colw;
            bp0 = *(const float2*)&attn[bh_row0 + (size_t)gid * S + colb];
            bp1 = *(const float2*)&attn[bh_row0 + (size_t)(gid + 8) * S + colb];
        }

        const int nc = warp * 8 + gid;    // this warp's 8 key-cols in the chunk
#pragma unroll
        for (int ks = 0; ks < 8; ks++) {
            const unsigned b0 = cur[nc * KSTK + ks * 8 + tig];
            const unsigned b1 = cur[nc * KSTK + ks * 8 + tig + 4];
            mma_tf32(acc, qa[ks][0], qa[ks][1], qa[ks][2], qa[ks][3], b0, b1);
        }

        // stage next K chunk into the other buffer
        if (kt < NCH - 1) {
            unsigned* nxt = KV + ((kt + 1) & 1) * BUFW;
#pragma unroll
            for (int p = 0; p < 4; p++) {
                const int i = tid + p * 256;
                uint4 u;
                u.x = f2tf(st[p].x); u.y = f2tf(st[p].y);
                u.z = f2tf(st[p].z); u.w = f2tf(st[p].w);
                *(uint4*)&nxt[(i >> 4) * KSTK + (i & 15) * 4] = u;
            }
        }

        // store logits tile (single write)
        const int colb = kt * CH + colw;
        *(float2*)&L[gid * LSTR + colb]       = make_float2(acc[0], acc[1]);
        *(float2*)&L[(gid + 8) * LSTR + colb] = make_float2(acc[2], acc[3]);
        __syncthreads();
    }

    // ---- preload V chunk 0 (overlaps softmax) ----
#pragma unroll
    for (int p = 0; p < 4; p++) {
        const int i = tid + p * 256;
        st[p] = *(const float4*)&Vb[(size_t)(i >> 4) * DA + (i & 15) * 4];
    }

    // ---- softmax: warp per 2 rows; write attn (float) + L (tf32 bits) ----
#pragma unroll
    for (int r = 0; r < 2; r++) {
        const int row = warp * 2 + r;
        float* Lr = &L[row * LSTR];
        float4 v[8];
        float m = -1e30f;
#pragma unroll
        for (int c = 0; c < 8; c++) {
            v[c] = *(float4*)&Lr[c * 128 + lane * 4];
            m = fmaxf(m, fmaxf(fmaxf(v[c].x, v[c].y), fmaxf(v[c].z, v[c].w)));
        }
#pragma unroll
        for (int o = 16; o; o >>= 1) m = fmaxf(m, __shfl_xor_sync(0xffffffffu, m, o));
        float s = 0.0f;
#pragma unroll
        for (int c = 0; c < 8; c++) {
            v[c].x = __expf(v[c].x - m); v[c].y = __expf(v[c].y - m);
            v[c].z = __expf(v[c].z - m); v[c].w = __expf(v[c].w - m);
            s += v[c].x + v[c].y + v[c].z + v[c].w;
        }
#pragma unroll
        for (int o = 16; o; o >>= 1) s += __shfl_xor_sync(0xffffffffu, s, o);
        const float inv = 1.0f / s;
        float* Ar = attn + bh_row0 + (size_t)row * S;
#pragma unroll
        for (int c = 0; c < 8; c++) {
            v[c].x *= inv; v[c].y *= inv; v[c].z *= inv; v[c].w *= inv;
            *(float4*)&Ar[c * 128 + lane * 4] = v[c];
            uint4 u;
            u.x = f2tf(v[c].x); u.y = f2tf(v[c].y);
            u.z = f2tf(v[c].z); u.w = f2tf(v[c].w);
            *(uint4*)&Lu[row * LSTR + c * 128 + lane * 4] = u;
        }
    }

    // stage V chunk 0 into buf0
#pragma unroll
    for (int p = 0; p < 4; p++) {
        const int i = tid + p * 256;
        uint4 u;
        u.x = f2tf(st[p].x); u.y = f2tf(st[p].y);
        u.z = f2tf(st[p].z); u.w = f2tf(st[p].w);
        *(uint4*)&KV[(i >> 4) * KSTV + (i & 15) * 4] = u;
    }
    __syncthreads();

    // ---- PV: ctx tile [16,64] = L @ V; ks halves across 2 warp groups ----
    const int wg  = warp >> 2;          // 0/1: which half of each chunk's k8-steps
    const int sub = warp & 3;
    const int wn  = sub * 16;           // 16 d-cols per warp (2 mma per A-frag)
    float pacc[2][4] = {};
    for (int kt = 0; kt < NCH; kt++) {
        const unsigned* cur = KV + (kt & 1) * BUFW;
        if (kt < NCH - 1) {
            const int kbase = (kt + 1) * CH;
#pragma unroll
            for (int p = 0; p < 4; p++) {
                const int i = tid + p * 256;
                st[p] = *(const float4*)&Vb[(size_t)(kbase + (i >> 4)) * DA + (i & 15) * 4];
            }
        }

#pragma unroll
        for (int ks = 0; ks < 4; ks++) {
            const int ksc = wg * 4 + ks;          // 0..7 k8-steps of this chunk
            const int kk  = kt * CH + ksc * 8;
            const unsigned a0 = Lu[gid * LSTR + kk + tig];
            const unsigned a1 = Lu[(gid + 8) * LSTR + kk + tig];
            const unsigned a2 = Lu[gid * LSTR + kk + tig + 4];
            const unsigned a3 = Lu[(gid + 8) * LSTR + kk + tig + 4];
#pragma unroll
            for (int ni = 0; ni < 2; ni++) {
                const unsigned b0 = cur[(ksc * 8 + tig) * KSTV + wn + ni * 8 + gid];
                const unsigned b1 = cur[(ksc * 8 + tig + 4) * KSTV + wn + ni * 8 + gid];
                mma_tf32(pacc[ni], a0, a1, a2, a3, b0, b1);
            }
        }

        if (kt < NCH - 1) {
            unsigned* nxt = KV + ((kt + 1) & 1) * BUFW;
#pragma unroll
            for (int p = 0; p < 4; p++) {
                const int i = tid + p * 256;
                uint4 u;
                u.x = f2tf(st[p].x); u.y = f2tf(st[p].y);
                u.z = f2tf(st[p].z); u.w = f2tf(st[p].w);
                *(uint4*)&nxt[(i >> 4) * KSTV + (i & 15) * 4] = u;
            }
        }
        __syncthreads();
    }

    // reduce the two ks-half partials and store ctx
    if (wg == 1) {
#pragma unroll
        for (int ni = 0; ni < 2; ni++) {
            const int col = wn + ni * 8 + tig * 2;
            *(float2*)&P[gid * QSTR + col]       = make_float2(pacc[ni][0], pacc[ni][1]);
            *(float2*)&P[(gid + 8) * QSTR + col] = make_float2(pacc[ni][2], pacc[ni][3]);
        }
    }
    __syncthreads();
    if (wg == 0) {
        const int grow = b * S + q0 + gid;
#pragma unroll
        for (int ni = 0; ni < 2; ni++) {
            const int col = wn + ni * 8 + tig * 2;
            const float2 p0 = *(const float2*)&P[gid * QSTR + col];
            const float2 p1 = *(const float2*)&P[(gid + 8) * QSTR + col];
            float2 o0, o1;
            o0.x = pacc[ni][0] + p0.x; o0.y = pacc[ni][1] + p0.y;
            o1.x = pacc[ni][2] + p1.x; o1.y = pacc[ni][3] + p1.y;
            *(float2*)&ctx[(size_t)grow * DA + h * 64 + col]       = o0;
            *(float2*)&ctx[(size_t)(grow + 8) * DA + h * 64 + col] = o1;
        }
    }
}

// ---------------------------------------------------------------------------
extern "C" void kernel_launch(void* const* d_in, const int* in_sizes, int n_in,
                              void* d_out, int out_size)
{
    const float* q     = (const float*)d_in[0];
    const float* k     = (const float*)d_in[1];
    const float* v     = (const float*)d_in[2];
    const float* xdiff = (const float*)d_in[3];
    const float* Wq    = (const float*)d_in[4];
    const float* bq    = (const float*)d_in[5];
    const float* Wk    = (const float*)d_in[6];
    const float* bk    = (const float*)d_in[7];
    const float* Wv    = (const float*)d_in[8];
    const float* bv    = (const float*)d_in[9];
    const float* Wx    = (const float*)d_in[10];
    const float* bx    = (const float*)d_in[11];
    const float* Wo    = (const float*)d_in[12];
    const float* bo    = (const float*)d_in[13];

    float* out_final = (float*)d_out;                       // [B,S,DM]
    float* attn      = out_final + (size_t)B * S * DM;      // [B,H,S,S]

    float *qp, *kp, *vp, *xg, *ctx;
    cudaGetSymbolAddress((void**)&qp,  g_qp);
    cudaGetSymbolAddress((void**)&kp,  g_kp);
    cudaGetSymbolAddress((void**)&vp,  g_vp);
    cudaGetSymbolAddress((void**)&xg,  g_x);
    cudaGetSymbolAddress((void**)&ctx, g_ctx);

    cudaFuncSetAttribute(fattn_kernel, cudaFuncAttributeMaxDynamicSharedMemorySize,
                         FATTN_SMEM);

    // 1. q/k/v projections, one batched launch
    qkv_proj_kernel<<<dim3(DA / 64, (B * S) / 64, 3), 128>>>(
        q, k, v, Wq, bq, Wk, bk, Wv, bv, qp, kp, vp);

    // 2. x = qp @ Wx + bx
    gemm64_kernel<<<dim3((H * F) / 64, (B * S) / 64), 128>>>(qp, Wx, bx, xg, H * F, DA);

    // 3. xdiff relative bias -> logits buffer (attn region)
    xbias_kernel<<<B * S, 256>>>(xdiff, xg, attn);

    // 4. fused: logits = bias + QK^T, softmax, attn out, PV -> ctx
    //    q-tile fast dim so consecutive CTAs share K/V in L2
    fattn_kernel<<<dim3(S / QT, B * H), 256, FATTN_SMEM>>>(qp, kp, vp, attn, ctx);

    // 5. output = ctx @ Wo + bo
    gemm64_kernel<<<dim3(DM / 64, (B * S) / 64), 128>>>(ctx, Wo, bo, out_final, DM, DA);
}

// round 12
// speedup vs baseline: 1.1221x; 1.1221x over previous
#include <cuda_runtime.h>

// Problem constants
namespace {
constexpr int B  = 4;
constexpr int S  = 1024;
constexpr int DM = 512;
constexpr int DA = 512;
constexpr int H  = 8;
constexpr int F  = 16;
}

// Scratch (static device globals -- no allocations allowed)
__device__ float g_qp [B * S * DA];      // 8 MB (tf32-rounded)
__device__ float g_kp [B * S * DA];      // 8 MB (tf32-rounded)
__device__ float g_vp [B * S * DA];      // 8 MB (tf32-rounded)
__device__ float g_x  [B * S * H * F];   // 2 MB
__device__ float g_ctx[B * S * DA];      // 8 MB

// ---------------------------------------------------------------------------
// tf32 helpers
// ---------------------------------------------------------------------------
__device__ __forceinline__ unsigned f2tf(float f) {
    unsigned u;
    asm("cvt.rna.tf32.f32 %0, %1;" : "=r"(u) : "f"(f));
    return u;
}

__device__ __forceinline__ void mma_tf32(float c[4],
                                         unsigned a0, unsigned a1, unsigned a2, unsigned a3,
                                         unsigned b0, unsigned b1) {
    asm volatile(
        "mma.sync.aligned.m16n8k8.row.col.f32.tf32.tf32.f32 "
        "{%0,%1,%2,%3}, {%4,%5,%6,%7}, {%8,%9}, {%0,%1,%2,%3};"
        : "+f"(c[0]), "+f"(c[1]), "+f"(c[2]), "+f"(c[3])
        : "r"(a0), "r"(a1), "r"(a2), "r"(a3), "r"(b0), "r"(b1));
}

// ---------------------------------------------------------------------------
// 64x64-tile tf32 GEMM body: C[m0:64, n0:64] = A[M,K] @ W[K,N] + bias
// 128 threads (4 warps, warp-tile 32x32), BK=16, reg-prefetch double buffer.
// TF32OUT: round the stored output to tf32 (for q/k/v projections, so the
// attention kernel can stage K/V/Q without conversions; numerically identical
// to converting at staging time).
// ---------------------------------------------------------------------------
template <bool TF32OUT>
__device__ __forceinline__ void gemm64_body(
    const float* __restrict__ A, const float* __restrict__ W,
    const float* __restrict__ bias, float* __restrict__ C,
    int N, int K, int m0, int n0)
{
    constexpr int AS = 20;   // As[m][k], 16+4
    constexpr int BS = 72;   // Bs[k][n], 64+8
    __shared__ unsigned As[64 * AS];
    __shared__ unsigned Bs[16 * BS];

    const int tid  = threadIdx.x;
    const int warp = tid >> 5;
    const int lane = tid & 31;
    const int gid  = lane >> 2;
    const int tig  = lane & 3;
    const int wm   = (warp & 1) * 32;
    const int wn   = (warp >> 1) * 32;

    float4 ra[2], rb[2];
#pragma unroll
    for (int p = 0; p < 2; p++) {
        const int ia = tid + p * 128;
        ra[p] = *(const float4*)&A[(size_t)(m0 + (ia >> 2)) * K + (ia & 3) * 4];
        const int ib = tid + p * 128;
        rb[p] = *(const float4*)&W[(size_t)(ib >> 4) * N + n0 + (ib & 15) * 4];
    }

    float acc[2][4][4] = {};

    for (int k0 = 0; k0 < K; k0 += 16) {
#pragma unroll
        for (int p = 0; p < 2; p++) {
            const int ia = tid + p * 128;
            unsigned* pa = &As[(ia >> 2) * AS + (ia & 3) * 4];
            pa[0] = f2tf(ra[p].x); pa[1] = f2tf(ra[p].y);
            pa[2] = f2tf(ra[p].z); pa[3] = f2tf(ra[p].w);
            const int ib = tid + p * 128;
            unsigned* pb = &Bs[(ib >> 4) * BS + (ib & 15) * 4];
            pb[0] = f2tf(rb[p].x); pb[1] = f2tf(rb[p].y);
            pb[2] = f2tf(rb[p].z); pb[3] = f2tf(rb[p].w);
        }
        __syncthreads();
        if (k0 + 16 < K) {
#pragma unroll
            for (int p = 0; p < 2; p++) {
                const int ia = tid + p * 128;
                ra[p] = *(const float4*)&A[(size_t)(m0 + (ia >> 2)) * K + k0 + 16 + (ia & 3) * 4];
                const int ib = tid + p * 128;
                rb[p] = *(const float4*)&W[(size_t)(k0 + 16 + (ib >> 4)) * N + n0 + (ib & 15) * 4];
            }
        }
#pragma unroll
        for (int ks = 0; ks < 2; ks++) {
            unsigned afr[2][4];
#pragma unroll
            for (int mi = 0; mi < 2; mi++) {
                const int mr = wm + mi * 16 + gid;
                afr[mi][0] = As[mr * AS + ks * 8 + tig];
                afr[mi][1] = As[(mr + 8) * AS + ks * 8 + tig];
                afr[mi][2] = As[mr * AS + ks * 8 + tig + 4];
                afr[mi][3] = As[(mr + 8) * AS + ks * 8 + tig + 4];
            }
            unsigned bfr[4][2];
#pragma unroll
            for (int ni = 0; ni < 4; ni++) {
                const int nc = wn + ni * 8 + gid;
                bfr[ni][0] = Bs[(ks * 8 + tig) * BS + nc];
                bfr[ni][1] = Bs[(ks * 8 + tig + 4) * BS + nc];
            }
#pragma unroll
            for (int mi = 0; mi < 2; mi++)
#pragma unroll
                for (int ni = 0; ni < 4; ni++)
                    mma_tf32(acc[mi][ni], afr[mi][0], afr[mi][1], afr[mi][2], afr[mi][3],
                             bfr[ni][0], bfr[ni][1]);
        }
        __syncthreads();
    }

#pragma unroll
    for (int mi = 0; mi < 2; mi++) {
        const int row = m0 + wm + mi * 16 + gid;
#pragma unroll
        for (int ni = 0; ni < 4; ni++) {
            const int col = n0 + wn + ni * 8 + 2 * tig;
            const float2 bb = *(const float2*)&bias[col];
            float2 o0, o1;
            o0.x = acc[mi][ni][0] + bb.x; o0.y = acc[mi][ni][1] + bb.y;
            o1.x = acc[mi][ni][2] + bb.x; o1.y = acc[mi][ni][3] + bb.y;
            if (TF32OUT) {
                o0.x = __uint_as_float(f2tf(o0.x)); o0.y = __uint_as_float(f2tf(o0.y));
                o1.x = __uint_as_float(f2tf(o1.x)); o1.y = __uint_as_float(f2tf(o1.y));
            }
            *(float2*)&C[(size_t)row * N + col]       = o0;
            *(float2*)&C[(size_t)(row + 8) * N + col] = o1;
        }
    }
}

// q/k/v projections batched over blockIdx.z (tf32-rounded outputs)
__global__ __launch_bounds__(128) void qkv_proj_kernel(
    const float* __restrict__ q, const float* __restrict__ k, const float* __restrict__ v,
    const float* __restrict__ Wq, const float* __restrict__ bq,
    const float* __restrict__ Wk, const float* __restrict__ bk,
    const float* __restrict__ Wv, const float* __restrict__ bv,
    float* __restrict__ qp, float* __restrict__ kp, float* __restrict__ vp)
{
    const int z = blockIdx.z;
    const float* A    = (z == 0) ? q  : (z == 1) ? k  : v;
    const float* W    = (z == 0) ? Wq : (z == 1) ? Wk : Wv;
    const float* bias = (z == 0) ? bq : (z == 1) ? bk : bv;
    float*       C    = (z == 0) ? qp : (z == 1) ? kp : vp;
    gemm64_body<true>(A, W, bias, C, DA, DM, blockIdx.y * 64, blockIdx.x * 64);
}

// generic single GEMM (x projection, output projection)
__global__ __launch_bounds__(128) void gemm64_kernel(
    const float* __restrict__ A, const float* __restrict__ W,
    const float* __restrict__ bias, float* __restrict__ C, int N, int K)
{
    gemm64_body<false>(A, W, bias, C, N, K, blockIdx.y * 64, blockIdx.x * 64);
}

// ---------------------------------------------------------------------------
// xdiff bias: logits[b,h,q,k] = 0.5 * sum_f xdiff[b,q,k,f] * x[b,q,h*F+f]
// ---------------------------------------------------------------------------
__global__ __launch_bounds__(256) void xbias_kernel(
    const float* __restrict__ xdiff, const float* __restrict__ xg,
    float* __restrict__ logits)
{
    __shared__ float xh[H * F];
    const int bq  = blockIdx.x;
    const int b   = bq >> 10;
    const int qi  = bq & 1023;
    const int tid = threadIdx.x;
    if (tid < H * F) xh[tid] = xg[(size_t)bq * (H * F) + tid];
    __syncthreads();
    const float* xd = xdiff + (size_t)bq * S * F;
#pragma unroll
    for (int kt = 0; kt < 4; kt++) {
        const int k = kt * 256 + tid;
        const float4* src = (const float4*)&xd[(size_t)k * F];
        const float4 t0 = src[0], t1 = src[1], t2 = src[2], t3 = src[3];
        const float xv[16] = {t0.x, t0.y, t0.z, t0.w, t1.x, t1.y, t1.z, t1.w,
                              t2.x, t2.y, t2.z, t2.w, t3.x, t3.y, t3.z, t3.w};
#pragma unroll
        for (int h = 0; h < H; h++) {
            float s = 0.0f;
#pragma unroll
            for (int f = 0; f < F; f++) s = fmaf(xv[f], xh[h * F + f], s);
            logits[((size_t)(b * H + h) * S + qi) * S + k] = 0.5f * s;
        }
    }
}

// ---------------------------------------------------------------------------
// Fused attention, 512 threads / 16 warps, double-buffered 128-key chunks.
// Inputs qp/kp/vp are tf32-pre-rounded -> staging is bit-copy (no cvt).
//   acc = bias (prefetched LDG) + QK^T (Q frags hoisted to regs) -> STS to L
//   softmax(L float) -> attn gmem (float) + L (tf32 bits)
//   PV: ks-split across 2 warp groups, smem partial reduce -> ctx
// smem: L 32x1044 + Qs/P 32x68 + 2 x (128x72 KV buffers) = 216,064 B
// ---------------------------------------------------------------------------
namespace {
constexpr int LSTR = 1044;
constexpr int QSTR = 68;
constexpr int KSTK = 68;   // K-phase layout stride inside buffer
constexpr int KSTV = 72;   // V-phase layout stride
constexpr int BUFW = 128 * KSTV;
constexpr int FATTN_SMEM = (32 * LSTR + 32 * QSTR + 2 * BUFW) * 4;
}

__global__ __launch_bounds__(512) void fattn_kernel(
    const float* __restrict__ qp, const float* __restrict__ kp,
    const float* __restrict__ vp, float* __restrict__ attn,
    float* __restrict__ ctx)
{
    extern __shared__ float smem[];
    float*    L  = smem;                               // 32 x LSTR (float / tf32 bits)
    unsigned* Lu = (unsigned*)smem;
    unsigned* Qs = (unsigned*)(smem + 32 * LSTR);      // 32 x QSTR (Q; later P partials)
    float*    P  = (float*)Qs;
    unsigned* KV = Qs + 32 * QSTR;                     // 2 x BUFW

    const int tid  = threadIdx.x;
    const int warp = tid >> 5;          // 0..15
    const int lane = tid & 31;
    const int gid  = lane >> 2;
    const int tig  = lane & 3;

    const int bh = blockIdx.y;           // b*H + h
    const int b  = bh >> 3;
    const int h  = bh & 7;
    const int q0 = blockIdx.x * 32;

    const size_t bh_row0 = ((size_t)bh * S + q0) * S;

    // ---- Q tile -> Qs (x0.125 is exact; values already tf32-rounded) ----
    {
        const int row = tid >> 4;
        const int c4  = (tid & 15) * 4;
        const float4 v = *(const float4*)&qp[(size_t)(b * S + q0 + row) * DA + h * 64 + c4];
        unsigned* p = &Qs[row * QSTR + c4];
        p[0] = __float_as_uint(v.x * 0.125f); p[1] = __float_as_uint(v.y * 0.125f);
        p[2] = __float_as_uint(v.z * 0.125f); p[3] = __float_as_uint(v.w * 0.125f);
    }
    __syncthreads();

    // ---- hoist Q fragments into registers (same for every chunk) ----
    unsigned qa[2][8][4];
#pragma unroll
    for (int mi = 0; mi < 2; mi++) {
        const int mr = mi * 16 + gid;
#pragma unroll
        for (int ks = 0; ks < 8; ks++) {
            qa[mi][ks][0] = Qs[mr * QSTR + ks * 8 + tig];
            qa[mi][ks][1] = Qs[(mr + 8) * QSTR + ks * 8 + tig];
            qa[mi][ks][2] = Qs[mr * QSTR + ks * 8 + tig + 4];
            qa[mi][ks][3] = Qs[(mr + 8) * QSTR + ks * 8 + tig + 4];
        }
    }

    const float* Kb = kp + (size_t)b * S * DA + h * 64;
    const float* Vb = vp + (size_t)b * S * DA + h * 64;

    uint4 st[4];

    // ---- preload K chunk 0 (bit-copy; already tf32) ----
#pragma unroll
    for (int p = 0; p < 4; p++) {
        const int i = tid + p * 512;
        st[p] = *(const uint4*)&Kb[(size_t)(i >> 4) * DA + (i & 15) * 4];
    }
#pragma unroll
    for (int p = 0; p < 4; p++) {
        const int i = tid + p * 512;
        *(uint4*)&KV[(i >> 4) * KSTK + (i & 15) * 4] = st[p];
    }

    // ---- prefetch bias for chunk 0 ----
    const int colw = warp * 8 + tig * 2;       // this warp's 8 cols within a chunk
    float2 bp[2][2];
#pragma unroll
    for (int mi = 0; mi < 2; mi++) {
        const int row = mi * 16 + gid;
        bp[mi][0] = *(const float2*)&attn[bh_row0 + (size_t)row * S + colw];
        bp[mi][1] = *(const float2*)&attn[bh_row0 + (size_t)(row + 8) * S + colw];
    }
    __syncthreads();

    // ---- QK^T: acc = bias + QK; result stored once to L ----
    for (int kt = 0; kt < 8; kt++) {
        const unsigned* cur = KV + (kt & 1) * BUFW;
        if (kt < 7) {
            const int kbase = (kt + 1) * 128;
#pragma unroll
            for (int p = 0; p < 4; p++) {
                const int i = tid + p * 512;
                st[p] = *(const uint4*)&Kb[(size_t)(kbase + (i >> 4)) * DA + (i & 15) * 4];
            }
        }

        float acc[2][4];
#pragma unroll
        for (int mi = 0; mi < 2; mi++) {
            acc[mi][0] = bp[mi][0].x; acc[mi][1] = bp[mi][0].y;
            acc[mi][2] = bp[mi][1].x; acc[mi][3] = bp[mi][1].y;
        }

        // prefetch bias for next chunk (overlaps mma loop)
        if (kt < 7) {
            const int colb = (kt + 1) * 128 + colw;
#pragma unroll
            for (int mi = 0; mi < 2; mi++) {
                const int row = mi * 16 + gid;
                bp[mi][0] = *(const float2*)&attn[bh_row0 + (size_t)row * S + colb];
                bp[mi][1] = *(const float2*)&attn[bh_row0 + (size_t)(row + 8) * S + colb];
            }
        }

#pragma unroll
        for (int ks = 0; ks < 8; ks++) {
            const int nc = warp * 8 + gid;
            const unsigned b0 = cur[nc * KSTK + ks * 8 + tig];
            const unsigned b1 = cur[nc * KSTK + ks * 8 + tig + 4];
            mma_tf32(acc[0], qa[0][ks][0], qa[0][ks][1], qa[0][ks][2], qa[0][ks][3], b0, b1);
            mma_tf32(acc[1], qa[1][ks][0], qa[1][ks][1], qa[1][ks][2], qa[1][ks][3], b0, b1);
        }

        if (kt < 7) {
            unsigned* nxt = KV + ((kt + 1) & 1) * BUFW;
#pragma unroll
            for (int p = 0; p < 4; p++) {
                const int i = tid + p * 512;
                *(uint4*)&nxt[(i >> 4) * KSTK + (i & 15) * 4] = st[p];
            }
        }

        // store logits tile (single write, no RMW)
        const int colb = kt * 128 + colw;
#pragma unroll
        for (int mi = 0; mi < 2; mi++) {
            const int row = mi * 16 + gid;
            *(float2*)&L[row * LSTR + colb]       = make_float2(acc[mi][0], acc[mi][1]);
            *(float2*)&L[(row + 8) * LSTR + colb] = make_float2(acc[mi][2], acc[mi][3]);
        }
        __syncthreads();
    }

    // ---- preload V chunk 0 (overlaps with softmax) ----
#pragma unroll
    for (int p = 0; p < 4; p++) {
        const int i = tid + p * 512;
        st[p] = *(const uint4*)&Vb[(size_t)(i >> 4) * DA + (i & 15) * 4];
    }

    // ---- softmax (warp per 2 rows): attn gmem (float) + L (tf32 bits) ----
#pragma unroll
    for (int r = 0; r < 2; r++) {
        const int row = warp * 2 + r;
        float* Lr = &L[row * LSTR];
        float4 v[8];
        float m = -1e30f;
#pragma unroll
        for (int c = 0; c < 8; c++) {
            v[c] = *(float4*)&Lr[c * 128 + lane * 4];
            m = fmaxf(m, fmaxf(fmaxf(v[c].x, v[c].y), fmaxf(v[c].z, v[c].w)));
        }
#pragma unroll
        for (int o = 16; o; o >>= 1) m = fmaxf(m, __shfl_xor_sync(0xffffffffu, m, o));
        float s = 0.0f;
#pragma unroll
        for (int c = 0; c < 8; c++) {
            v[c].x = __expf(v[c].x - m); v[c].y = __expf(v[c].y - m);
            v[c].z = __expf(v[c].z - m); v[c].w = __expf(v[c].w - m);
            s += v[c].x + v[c].y + v[c].z + v[c].w;
        }
#pragma unroll
        for (int o = 16; o; o >>= 1) s += __shfl_xor_sync(0xffffffffu, s, o);
        const float inv = 1.0f / s;
        float* Ar = attn + bh_row0 + (size_t)row * S;
#pragma unroll
        for (int c = 0; c < 8; c++) {
            v[c].x *= inv; v[c].y *= inv; v[c].z *= inv; v[c].w *= inv;
            *(float4*)&Ar[c * 128 + lane * 4] = v[c];
            uint4 u;
            u.x = f2tf(v[c].x); u.y = f2tf(v[c].y);
            u.z = f2tf(v[c].z); u.w = f2tf(v[c].w);
            *(uint4*)&Lu[row * LSTR + c * 128 + lane * 4] = u;
        }
    }

    // store V chunk 0 into buf0
#pragma unroll
    for (int p = 0; p < 4; p++) {
        const int i = tid + p * 512;
        *(uint4*)&KV[(i >> 4) * KSTV + (i & 15) * 4] = st[p];
    }
    __syncthreads();

    // ---- PV: ctx tile [32,64] = L @ V; ks split across 2 warp groups ----
    const int wg  = warp >> 3;          // 0/1: which half of each chunk's keys
    const int sub = warp & 7;
    const int mi  = sub & 1;
    const int wn  = (sub >> 1) * 16;    // 16 cols per warp (2 mma per A-frag)
    const int row = mi * 16 + gid;
    float pacc[2][4] = {};
    for (int kt = 0; kt < 8; kt++) {
        const unsigned* cur = KV + (kt & 1) * BUFW;
        if (kt < 7) {
            const int kbase = (kt + 1) * 128;
#pragma unroll
            for (int p = 0; p < 4; p++) {
                const int i = tid + p * 512;
                st[p] = *(const uint4*)&Vb[(size_t)(kbase + (i >> 4)) * DA + (i & 15) * 4];
            }
        }

#pragma unroll
        for (int ks = 0; ks < 8; ks++) {
            const int ksc = wg * 8 + ks;
            const int kk  = kt * 128 + ksc * 8;
            const unsigned a0 = Lu[row * LSTR + kk + tig];
            const unsigned a1 = Lu[(row + 8) * LSTR + kk + tig];
            const unsigned a2 = Lu[row * LSTR + kk + tig + 4];
            const unsigned a3 = Lu[(row + 8) * LSTR + kk + tig + 4];
#pragma unroll
            for (int ni = 0; ni < 2; ni++) {
                const unsigned b0 = cur[(ksc * 8 + tig) * KSTV + wn + ni * 8 + gid];
                const unsigned b1 = cur[(ksc * 8 + tig + 4) * KSTV + wn + ni * 8 + gid];
                mma_tf32(pacc[ni], a0, a1, a2, a3, b0, b1);
            }
        }

        if (kt < 7) {
            unsigned* nxt = KV + ((kt + 1) & 1) * BUFW;
#pragma unroll
            for (int p = 0; p < 4; p++) {
                const int i = tid + p * 512;
                *(uint4*)&nxt[(i >> 4) * KSTV + (i & 15) * 4] = st[p];
            }
        }
        __syncthreads();
    }

    // reduce the two ks-half partials and store ctx
    if (wg == 1) {
#pragma unroll
        for (int ni = 0; ni < 2; ni++) {
            const int col = wn + ni * 8 + tig * 2;
            *(float2*)&P[row * QSTR + col]       = make_float2(pacc[ni][0], pacc[ni][1]);
            *(float2*)&P[(row + 8) * QSTR + col] = make_float2(pacc[ni][2], pacc[ni][3]);
        }
    }
    __syncthreads();
    if (wg == 0) {
        const int grow = b * S + q0 + row;
#pragma unroll
        for (int ni = 0; ni < 2; ni++) {
            const int col = wn + ni * 8 + tig * 2;
            const float2 p0 = *(const float2*)&P[row * QSTR + col];
            const float2 p1 = *(const float2*)&P[(row + 8) * QSTR + col];
            float2 o0, o1;
            o0.x = pacc[ni][0] + p0.x; o0.y = pacc[ni][1] + p0.y;
            o1.x = pacc[ni][2] + p1.x; o1.y = pacc[ni][3] + p1.y;
            *(float2*)&ctx[(size_t)grow * DA + h * 64 + col]       = o0;
            *(float2*)&ctx[(size_t)(grow + 8) * DA + h * 64 + col] = o1;
        }
    }
}

// ---------------------------------------------------------------------------
extern "C" void kernel_launch(void* const* d_in, const int* in_sizes, int n_in,
                              void* d_out, int out_size)
{
    const float* q     = (const float*)d_in[0];
    const float* k     = (const float*)d_in[1];
    const float* v     = (const float*)d_in[2];
    const float* xdiff = (const float*)d_in[3];
    const float* Wq    = (const float*)d_in[4];
    const float* bq    = (const float*)d_in[5];
    const float* Wk    = (const float*)d_in[6];
    const float* bk    = (const float*)d_in[7];
    const float* Wv    = (const float*)d_in[8];
    const float* bv    = (const float*)d_in[9];
    const float* Wx    = (const float*)d_in[10];
    const float* bx    = (const float*)d_in[11];
    const float* Wo    = (const float*)d_in[12];
    const float* bo    = (const float*)d_in[13];

    float* out_final = (float*)d_out;                       // [B,S,DM]
    float* attn      = out_final + (size_t)B * S * DM;      // [B,H,S,S]

    float *qp, *kp, *vp, *xg, *ctx;
    cudaGetSymbolAddress((void**)&qp,  g_qp);
    cudaGetSymbolAddress((void**)&kp,  g_kp);
    cudaGetSymbolAddress((void**)&vp,  g_vp);
    cudaGetSymbolAddress((void**)&xg,  g_x);
    cudaGetSymbolAddress((void**)&ctx, g_ctx);

    cudaFuncSetAttribute(fattn_kernel, cudaFuncAttributeMaxDynamicSharedMemorySize,
                         FATTN_SMEM);

    // 1. q/k/v projections, one batched launch (tf32-rounded outputs)
    qkv_proj_kernel<<<dim3(DA / 64, (B * S) / 64, 3), 128>>>(
        q, k, v, Wq, bq, Wk, bk, Wv, bv, qp, kp, vp);

    // 2. x = qp @ Wx + bx
    gemm64_kernel<<<dim3((H * F) / 64, (B * S) / 64), 128>>>(qp, Wx, bx, xg, H * F, DA);

    // 3. xdiff relative bias -> logits buffer (attn region)
    xbias_kernel<<<B * S, 256>>>(xdiff, xg, attn);

    // 4. fused: logits = bias + QK^T, softmax, attn out, PV -> ctx
    fattn_kernel<<<dim3(S / 32, B * H), 512, FATTN_SMEM>>>(qp, kp, vp, attn, ctx);

    // 5. output = ctx @ Wo + bo
    gemm64_kernel<<<dim3(DM / 64, (B * S) / 64), 128>>>(ctx, Wo, bo, out_final, DM, DA);
}

// round 13
// speedup vs baseline: 1.2048x; 1.0737x over previous
#include <cuda_runtime.h>

// Problem constants
namespace {
constexpr int B  = 4;
constexpr int S  = 1024;
constexpr int DM = 512;
constexpr int DA = 512;
constexpr int H  = 8;
constexpr int F  = 16;
}

// Scratch (static device globals -- no allocations allowed)
__device__ float g_qp [B * S * DA];      // 8 MB (tf32-rounded)
__device__ float g_kp [B * S * DA];      // 8 MB (tf32-rounded)
__device__ float g_vp [B * S * DA];      // 8 MB (tf32-rounded)
__device__ float g_x  [B * S * H * F];   // 2 MB
__device__ float g_ctx[B * S * DA];      // 8 MB

// ---------------------------------------------------------------------------
// tf32 / cp.async helpers
// ---------------------------------------------------------------------------
__device__ __forceinline__ unsigned f2tf(float f) {
    unsigned u;
    asm("cvt.rna.tf32.f32 %0, %1;" : "=r"(u) : "f"(f));
    return u;
}

__device__ __forceinline__ void mma_tf32(float c[4],
                                         unsigned a0, unsigned a1, unsigned a2, unsigned a3,
                                         unsigned b0, unsigned b1) {
    asm volatile(
        "mma.sync.aligned.m16n8k8.row.col.f32.tf32.tf32.f32 "
        "{%0,%1,%2,%3}, {%4,%5,%6,%7}, {%8,%9}, {%0,%1,%2,%3};"
        : "+f"(c[0]), "+f"(c[1]), "+f"(c[2]), "+f"(c[3])
        : "r"(a0), "r"(a1), "r"(a2), "r"(a3), "r"(b0), "r"(b1));
}

__device__ __forceinline__ void cp16(void* dst_smem, const void* src_gmem) {
    const unsigned s = (unsigned)__cvta_generic_to_shared(dst_smem);
    asm volatile("cp.async.cg.shared.global [%0], [%1], 16;" :: "r"(s), "l"(src_gmem));
}
#define CP_COMMIT() asm volatile("cp.async.commit_group;")
#define CP_WAIT0()  asm volatile("cp.async.wait_group 0;" ::: "memory")

// ---------------------------------------------------------------------------
// 64x64-tile tf32 GEMM body: C[m0:64, n0:64] = A[M,K] @ W[K,N] + bias
// 128 threads (4 warps, warp-tile 32x32), BK=16, reg-prefetch double buffer.
// TF32OUT: round stored output to tf32 (for q/k/v projections).
// ---------------------------------------------------------------------------
template <bool TF32OUT>
__device__ __forceinline__ void gemm64_body(
    const float* __restrict__ A, const float* __restrict__ W,
    const float* __restrict__ bias, float* __restrict__ C,
    int N, int K, int m0, int n0)
{
    constexpr int AS = 20;   // As[m][k], 16+4
    constexpr int BS = 72;   // Bs[k][n], 64+8
    __shared__ unsigned As[64 * AS];
    __shared__ unsigned Bs[16 * BS];

    const int tid  = threadIdx.x;
    const int warp = tid >> 5;
    const int lane = tid & 31;
    const int gid  = lane >> 2;
    const int tig  = lane & 3;
    const int wm   = (warp & 1) * 32;
    const int wn   = (warp >> 1) * 32;

    float4 ra[2], rb[2];
#pragma unroll
    for (int p = 0; p < 2; p++) {
        const int ia = tid + p * 128;
        ra[p] = *(const float4*)&A[(size_t)(m0 + (ia >> 2)) * K + (ia & 3) * 4];
        const int ib = tid + p * 128;
        rb[p] = *(const float4*)&W[(size_t)(ib >> 4) * N + n0 + (ib & 15) * 4];
    }

    float acc[2][4][4] = {};

    for (int k0 = 0; k0 < K; k0 += 16) {
#pragma unroll
        for (int p = 0; p < 2; p++) {
            const int ia = tid + p * 128;
            unsigned* pa = &As[(ia >> 2) * AS + (ia & 3) * 4];
            pa[0] = f2tf(ra[p].x); pa[1] = f2tf(ra[p].y);
            pa[2] = f2tf(ra[p].z); pa[3] = f2tf(ra[p].w);
            const int ib = tid + p * 128;
            unsigned* pb = &Bs[(ib >> 4) * BS + (ib & 15) * 4];
            pb[0] = f2tf(rb[p].x); pb[1] = f2tf(rb[p].y);
            pb[2] = f2tf(rb[p].z); pb[3] = f2tf(rb[p].w);
        }
        __syncthreads();
        if (k0 + 16 < K) {
#pragma unroll
            for (int p = 0; p < 2; p++) {
                const int ia = tid + p * 128;
                ra[p] = *(const float4*)&A[(size_t)(m0 + (ia >> 2)) * K + k0 + 16 + (ia & 3) * 4];
                const int ib = tid + p * 128;
                rb[p] = *(const float4*)&W[(size_t)(k0 + 16 + (ib >> 4)) * N + n0 + (ib & 15) * 4];
            }
        }
#pragma unroll
        for (int ks = 0; ks < 2; ks++) {
            unsigned afr[2][4];
#pragma unroll
            for (int mi = 0; mi < 2; mi++) {
                const int mr = wm + mi * 16 + gid;
                afr[mi][0] = As[mr * AS + ks * 8 + tig];
                afr[mi][1] = As[(mr + 8) * AS + ks * 8 + tig];
                afr[mi][2] = As[mr * AS + ks * 8 + tig + 4];
                afr[mi][3] = As[(mr + 8) * AS + ks * 8 + tig + 4];
            }
            unsigned bfr[4][2];
#pragma unroll
            for (int ni = 0; ni < 4; ni++) {
                const int nc = wn + ni * 8 + gid;
                bfr[ni][0] = Bs[(ks * 8 + tig) * BS + nc];
                bfr[ni][1] = Bs[(ks * 8 + tig + 4) * BS + nc];
            }
#pragma unroll
            for (int mi = 0; mi < 2; mi++)
#pragma unroll
                for (int ni = 0; ni < 4; ni++)
                    mma_tf32(acc[mi][ni], afr[mi][0], afr[mi][1], afr[mi][2], afr[mi][3],
                             bfr[ni][0], bfr[ni][1]);
        }
        __syncthreads();
    }

#pragma unroll
    for (int mi = 0; mi < 2; mi++) {
        const int row = m0 + wm + mi * 16 + gid;
#pragma unroll
        for (int ni = 0; ni < 4; ni++) {
            const int col = n0 + wn + ni * 8 + 2 * tig;
            const float2 bb = *(const float2*)&bias[col];
            float2 o0, o1;
            o0.x = acc[mi][ni][0] + bb.x; o0.y = acc[mi][ni][1] + bb.y;
            o1.x = acc[mi][ni][2] + bb.x; o1.y = acc[mi][ni][3] + bb.y;
            if (TF32OUT) {
                o0.x = __uint_as_float(f2tf(o0.x)); o0.y = __uint_as_float(f2tf(o0.y));
                o1.x = __uint_as_float(f2tf(o1.x)); o1.y = __uint_as_float(f2tf(o1.y));
            }
            *(float2*)&C[(size_t)row * N + col]       = o0;
            *(float2*)&C[(size_t)(row + 8) * N + col] = o1;
        }
    }
}

// q/k/v projections batched over blockIdx.z (tf32-rounded outputs)
__global__ __launch_bounds__(128) void qkv_proj_kernel(
    const float* __restrict__ q, const float* __restrict__ k, const float* __restrict__ v,
    const float* __restrict__ Wq, const float* __restrict__ bq,
    const float* __restrict__ Wk, const float* __restrict__ bk,
    const float* __restrict__ Wv, const float* __restrict__ bv,
    float* __restrict__ qp, float* __restrict__ kp, float* __restrict__ vp)
{
    const int z = blockIdx.z;
    const float* A    = (z == 0) ? q  : (z == 1) ? k  : v;
    const float* W    = (z == 0) ? Wq : (z == 1) ? Wk : Wv;
    const float* bias = (z == 0) ? bq : (z == 1) ? bk : bv;
    float*       C    = (z == 0) ? qp : (z == 1) ? kp : vp;
    gemm64_body<true>(A, W, bias, C, DA, DM, blockIdx.y * 64, blockIdx.x * 64);
}

// generic single GEMM (x projection, output projection)
__global__ __launch_bounds__(128) void gemm64_kernel(
    const float* __restrict__ A, const float* __restrict__ W,
    const float* __restrict__ bias, float* __restrict__ C, int N, int K)
{
    gemm64_body<false>(A, W, bias, C, N, K, blockIdx.y * 64, blockIdx.x * 64);
}

// ---------------------------------------------------------------------------
// xdiff bias: logits[b,h,q,k] = 0.5 * sum_f xdiff[b,q,k,f] * x[b,q,h*F+f]
// ---------------------------------------------------------------------------
__global__ __launch_bounds__(256) void xbias_kernel(
    const float* __restrict__ xdiff, const float* __restrict__ xg,
    float* __restrict__ logits)
{
    __shared__ float xh[H * F];
    const int bq  = blockIdx.x;
    const int b   = bq >> 10;
    const int qi  = bq & 1023;
    const int tid = threadIdx.x;
    if (tid < H * F) xh[tid] = xg[(size_t)bq * (H * F) + tid];
    __syncthreads();
    const float* xd = xdiff + (size_t)bq * S * F;
#pragma unroll
    for (int kt = 0; kt < 4; kt++) {
        const int k = kt * 256 + tid;
        const float4* src = (const float4*)&xd[(size_t)k * F];
        const float4 t0 = src[0], t1 = src[1], t2 = src[2], t3 = src[3];
        const float xv[16] = {t0.x, t0.y, t0.z, t0.w, t1.x, t1.y, t1.z, t1.w,
                              t2.x, t2.y, t2.z, t2.w, t3.x, t3.y, t3.z, t3.w};
#pragma unroll
        for (int h = 0; h < H; h++) {
            float s = 0.0f;
#pragma unroll
            for (int f = 0; f < F; f++) s = fmaf(xv[f], xh[h * F + f], s);
            logits[((size_t)(b * H + h) * S + qi) * S + k] = 0.5f * s;
        }
    }
}

// ---------------------------------------------------------------------------
// Fused attention, 512 threads / 16 warps, cp.async double-buffered chunks.
// Inputs qp/kp/vp are tf32-pre-rounded -> staging is a pure 16B cp.async copy.
//   acc = bias (prefetched LDG) + QK^T (Q frags hoisted) -> STS to L
//   softmax(L float) -> attn gmem (float) + L (tf32 bits)
//   PV: q(2) x d-half(2x32col) x ks-quarter(4) split; 4-way partial reduce
//       through the freed KV smem region.
// smem: L 32x1044 + Qs 32x68 + 2 x (128x72 KV buffers) = 216,064 B
// ---------------------------------------------------------------------------
namespace {
constexpr int LSTR = 1044;
constexpr int QSTR = 68;
constexpr int KSTK = 68;   // K-phase layout stride inside buffer
constexpr int KSTV = 72;   // V-phase layout stride
constexpr int BUFW = 128 * KSTV;
constexpr int PSTR = 72;   // partial-reduce scratch stride
constexpr int FATTN_SMEM = (32 * LSTR + 32 * QSTR + 2 * BUFW) * 4;
}

__global__ __launch_bounds__(512) void fattn_kernel(
    const float* __restrict__ qp, const float* __restrict__ kp,
    const float* __restrict__ vp, float* __restrict__ attn,
    float* __restrict__ ctx)
{
    extern __shared__ float smem[];
    float*    L  = smem;                               // 32 x LSTR (float / tf32 bits)
    unsigned* Lu = (unsigned*)smem;
    unsigned* Qs = (unsigned*)(smem + 32 * LSTR);      // 32 x QSTR
    unsigned* KV = Qs + 32 * QSTR;                     // 2 x BUFW

    const int tid  = threadIdx.x;
    const int warp = tid >> 5;          // 0..15
    const int lane = tid & 31;
    const int gid  = lane >> 2;
    const int tig  = lane & 3;

    const int bh = blockIdx.y;           // b*H + h
    const int b  = bh >> 3;
    const int h  = bh & 7;
    const int q0 = blockIdx.x * 32;

    const size_t bh_row0 = ((size_t)bh * S + q0) * S;

    const float* Kb = kp + (size_t)b * S * DA + h * 64;
    const float* Vb = vp + (size_t)b * S * DA + h * 64;

    // ---- issue cp.async for K chunk 0 ----
#pragma unroll
    for (int p = 0; p < 4; p++) {
        const int i = tid + p * 512;
        cp16(&KV[(i >> 4) * KSTK + (i & 15) * 4], &Kb[(size_t)(i >> 4) * DA + (i & 15) * 4]);
    }
    CP_COMMIT();

    // ---- Q tile -> Qs (x0.125 exact; values already tf32-rounded) ----
    {
        const int row = tid >> 4;
        const int c4  = (tid & 15) * 4;
        const float4 v = *(const float4*)&qp[(size_t)(b * S + q0 + row) * DA + h * 64 + c4];
        unsigned* p = &Qs[row * QSTR + c4];
        p[0] = __float_as_uint(v.x * 0.125f); p[1] = __float_as_uint(v.y * 0.125f);
        p[2] = __float_as_uint(v.z * 0.125f); p[3] = __float_as_uint(v.w * 0.125f);
    }

    // ---- prefetch bias for chunk 0 ----
    const int colw = warp * 8 + tig * 2;       // this warp's 8 cols within a chunk
    float2 bp[2][2];
#pragma unroll
    for (int mi = 0; mi < 2; mi++) {
        const int row = mi * 16 + gid;
        bp[mi][0] = *(const float2*)&attn[bh_row0 + (size_t)row * S + colw];
        bp[mi][1] = *(const float2*)&attn[bh_row0 + (size_t)(row + 8) * S + colw];
    }
    CP_WAIT0();
    __syncthreads();

    // ---- hoist Q fragments into registers ----
    unsigned qa[2][8][4];
#pragma unroll
    for (int mi = 0; mi < 2; mi++) {
        const int mr = mi * 16 + gid;
#pragma unroll
        for (int ks = 0; ks < 8; ks++) {
            qa[mi][ks][0] = Qs[mr * QSTR + ks * 8 + tig];
            qa[mi][ks][1] = Qs[(mr + 8) * QSTR + ks * 8 + tig];
            qa[mi][ks][2] = Qs[mr * QSTR + ks * 8 + tig + 4];
            qa[mi][ks][3] = Qs[(mr + 8) * QSTR + ks * 8 + tig + 4];
        }
    }

    // ---- QK^T: acc = bias + QK; result stored once to L ----
    for (int kt = 0; kt < 8; kt++) {
        const unsigned* cur = KV + (kt & 1) * BUFW;

        if (kt < 7) {
            unsigned* nxt = KV + ((kt + 1) & 1) * BUFW;
            const int kbase = (kt + 1) * 128;
#pragma unroll
            for (int p = 0; p < 4; p++) {
                const int i = tid + p * 512;
                cp16(&nxt[(i >> 4) * KSTK + (i & 15) * 4],
                     &Kb[(size_t)(kbase + (i >> 4)) * DA + (i & 15) * 4]);
            }
            CP_COMMIT();
        }

        float acc[2][4];
#pragma unroll
        for (int mi = 0; mi < 2; mi++) {
            acc[mi][0] = bp[mi][0].x; acc[mi][1] = bp[mi][0].y;
            acc[mi][2] = bp[mi][1].x; acc[mi][3] = bp[mi][1].y;
        }

        // prefetch bias for next chunk (overlaps mma loop)
        if (kt < 7) {
            const int colb = (kt + 1) * 128 + colw;
#pragma unroll
            for (int mi = 0; mi < 2; mi++) {
                const int row = mi * 16 + gid;
                bp[mi][0] = *(const float2*)&attn[bh_row0 + (size_t)row * S + colb];
                bp[mi][1] = *(const float2*)&attn[bh_row0 + (size_t)(row + 8) * S + colb];
            }
        }

#pragma unroll
        for (int ks = 0; ks < 8; ks++) {
            const int nc = warp * 8 + gid;
            const unsigned b0 = cur[nc * KSTK + ks * 8 + tig];
            const unsigned b1 = cur[nc * KSTK + ks * 8 + tig + 4];
            mma_tf32(acc[0], qa[0][ks][0], qa[0][ks][1], qa[0][ks][2], qa[0][ks][3], b0, b1);
            mma_tf32(acc[1], qa[1][ks][0], qa[1][ks][1], qa[1][ks][2], qa[1][ks][3], b0, b1);
        }

        // store logits tile (single write, no RMW)
        const int colb = kt * 128 + colw;
#pragma unroll
        for (int mi = 0; mi < 2; mi++) {
            const int row = mi * 16 + gid;
            *(float2*)&L[row * LSTR + colb]       = make_float2(acc[mi][0], acc[mi][1]);
            *(float2*)&L[(row + 8) * LSTR + colb] = make_float2(acc[mi][2], acc[mi][3]);
        }
        if (kt < 7) CP_WAIT0();
        __syncthreads();
    }

    // ---- issue cp.async for V chunk 0 (overlaps softmax) ----
#pragma unroll
    for (int p = 0; p < 4; p++) {
        const int i = tid + p * 512;
        cp16(&KV[(i >> 4) * KSTV + (i & 15) * 4], &Vb[(size_t)(i >> 4) * DA + (i & 15) * 4]);
    }
    CP_COMMIT();

    // ---- softmax (warp per 2 rows): attn gmem (float) + L (tf32 bits) ----
#pragma unroll
    for (int r = 0; r < 2; r++) {
        const int row = warp * 2 + r;
        float* Lr = &L[row * LSTR];
        float4 v[8];
        float m = -1e30f;
#pragma unroll
        for (int c = 0; c < 8; c++) {
            v[c] = *(float4*)&Lr[c * 128 + lane * 4];
            m = fmaxf(m, fmaxf(fmaxf(v[c].x, v[c].y), fmaxf(v[c].z, v[c].w)));
        }
#pragma unroll
        for (int o = 16; o; o >>= 1) m = fmaxf(m, __shfl_xor_sync(0xffffffffu, m, o));
        float s = 0.0f;
#pragma unroll
        for (int c = 0; c < 8; c++) {
            v[c].x = __expf(v[c].x - m); v[c].y = __expf(v[c].y - m);
            v[c].z = __expf(v[c].z - m); v[c].w = __expf(v[c].w - m);
            s += v[c].x + v[c].y + v[c].z + v[c].w;
        }
#pragma unroll
        for (int o = 16; o; o >>= 1) s += __shfl_xor_sync(0xffffffffu, s, o);
        const float inv = 1.0f / s;
        float* Ar = attn + bh_row0 + (size_t)row * S;
#pragma unroll
        for (int c = 0; c < 8; c++) {
            v[c].x *= inv; v[c].y *= inv; v[c].z *= inv; v[c].w *= inv;
            *(float4*)&Ar[c * 128 + lane * 4] = v[c];
            uint4 u;
            u.x = f2tf(v[c].x); u.y = f2tf(v[c].y);
            u.z = f2tf(v[c].z); u.w = f2tf(v[c].w);
            *(uint4*)&Lu[row * LSTR + c * 128 + lane * 4] = u;
        }
    }
    CP_WAIT0();
    __syncthreads();

    // ---- PV: ctx tile [32,64] = L @ V ----
    // warp = (wg: ks-quarter) x (mi: q half) x (wn: d half of 32 cols)
    const int wg  = warp >> 2;          // 0..3: which quarter of each chunk's k8-steps
    const int sub = warp & 3;
    const int mi  = sub & 1;
    const int wn  = (sub >> 1) * 32;    // 32 d-cols per warp (4 mma per A-frag)
    const int row = mi * 16 + gid;
    float pacc[4][4] = {};
    for (int kt = 0; kt < 8; kt++) {
        const unsigned* cur = KV + (kt & 1) * BUFW;
        if (kt < 7) {
            unsigned* nxt = KV + ((kt + 1) & 1) * BUFW;
            const int kbase = (kt + 1) * 128;
#pragma unroll
            for (int p = 0; p < 4; p++) {
                const int i = tid + p * 512;
                cp16(&nxt[(i >> 4) * KSTV + (i & 15) * 4],
                     &Vb[(size_t)(kbase + (i >> 4)) * DA + (i & 15) * 4]);
            }
            CP_COMMIT();
        }

#pragma unroll
        for (int ks = 0; ks < 4; ks++) {
            const int ksc = wg * 4 + ks;              // 0..15 k8-steps of this chunk
            const int kk  = kt * 128 + ksc * 8;
            const unsigned a0 = Lu[row * LSTR + kk + tig];
            const unsigned a1 = Lu[(row + 8) * LSTR + kk + tig];
            const unsigned a2 = Lu[row * LSTR + kk + tig + 4];
            const unsigned a3 = Lu[(row + 8) * LSTR + kk + tig + 4];
#pragma unroll
            for (int ni = 0; ni < 4; ni++) {
                const unsigned b0 = cur[(ksc * 8 + tig) * KSTV + wn + ni * 8 + gid];
                const unsigned b1 = cur[(ksc * 8 + tig + 4) * KSTV + wn + ni * 8 + gid];
                mma_tf32(pacc[ni], a0, a1, a2, a3, b0, b1);
            }
        }
        if (kt < 7) CP_WAIT0();
        __syncthreads();
    }

    // ---- 4-way partial reduction through freed KV smem, then store ctx ----
    float* Pp = (float*)KV;             // scratch: 3 regions of 32 x PSTR
    if (wg != 0) {
        const int base = (wg - 1) * (32 * PSTR);
#pragma unroll
        for (int ni = 0; ni < 4; ni++) {
            const int col = wn + ni * 8 + tig * 2;
            *(float2*)&Pp[base + row * PSTR + col]       = make_float2(pacc[ni][0], pacc[ni][1]);
            *(float2*)&Pp[base + (row + 8) * PSTR + col] = make_float2(pacc[ni][2], pacc[ni][3]);
        }
    }
    __syncthreads();
    if (wg == 0) {
        const int grow = b * S + q0 + row;
#pragma unroll
        for (int ni = 0; ni < 4; ni++) {
            const int col = wn + ni * 8 + tig * 2;
            float2 o0 = make_float2(pacc[ni][0], pacc[ni][1]);
            float2 o1 = make_float2(pacc[ni][2], pacc[ni][3]);
#pragma unroll
            for (int r = 0; r < 3; r++) {
                const int base = r * (32 * PSTR);
                const float2 p0 = *(const float2*)&Pp[base + row * PSTR + col];
                const float2 p1 = *(const float2*)&Pp[base + (row + 8) * PSTR + col];
                o0.x += p0.x; o0.y += p0.y;
                o1.x += p1.x; o1.y += p1.y;
            }
            *(float2*)&ctx[(size_t)grow * DA + h * 64 + col]       = o0;
            *(float2*)&ctx[(size_t)(grow + 8) * DA + h * 64 + col] = o1;
        }
    }
}

// ---------------------------------------------------------------------------
extern "C" void kernel_launch(void* const* d_in, const int* in_sizes, int n_in,
                              void* d_out, int out_size)
{
    const float* q     = (const float*)d_in[0];
    const float* k     = (const float*)d_in[1];
    const float* v     = (const float*)d_in[2];
    const float* xdiff = (const float*)d_in[3];
    const float* Wq    = (const float*)d_in[4];
    const float* bq    = (const float*)d_in[5];
    const float* Wk    = (const float*)d_in[6];
    const float* bk    = (const float*)d_in[7];
    const float* Wv    = (const float*)d_in[8];
    const float* bv    = (const float*)d_in[9];
    const float* Wx    = (const float*)d_in[10];
    const float* bx    = (const float*)d_in[11];
    const float* Wo    = (const float*)d_in[12];
    const float* bo    = (const float*)d_in[13];

    float* out_final = (float*)d_out;                       // [B,S,DM]
    float* attn      = out_final + (size_t)B * S * DM;      // [B,H,S,S]

    float *qp, *kp, *vp, *xg, *ctx;
    cudaGetSymbolAddress((void**)&qp,  g_qp);
    cudaGetSymbolAddress((void**)&kp,  g_kp);
    cudaGetSymbolAddress((void**)&vp,  g_vp);
    cudaGetSymbolAddress((void**)&xg,  g_x);
    cudaGetSymbolAddress((void**)&ctx, g_ctx);

    cudaFuncSetAttribute(fattn_kernel, cudaFuncAttributeMaxDynamicSharedMemorySize,
                         FATTN_SMEM);

    // 1. q/k/v projections, one batched launch (tf32-rounded outputs)
    qkv_proj_kernel<<<dim3(DA / 64, (B * S) / 64, 3), 128>>>(
        q, k, v, Wq, bq, Wk, bk, Wv, bv, qp, kp, vp);

    // 2. x = qp @ Wx + bx
    gemm64_kernel<<<dim3((H * F) / 64, (B * S) / 64), 128>>>(qp, Wx, bx, xg, H * F, DA);

    // 3. xdiff relative bias -> logits buffer (attn region)
    xbias_kernel<<<B * S, 256>>>(xdiff, xg, attn);

    // 4. fused: logits = bias + QK^T, softmax, attn out, PV -> ctx
    fattn_kernel<<<dim3(S / 32, B * H), 512, FATTN_SMEM>>>(qp, kp, vp, attn, ctx);

    // 5. output = ctx @ Wo + bo
    gemm64_kernel<<<dim3(DM / 64, (B * S) / 64), 128>>>(ctx, Wo, bo, out_final, DM, DA);
}